// round 13
// baseline (speedup 1.0000x reference)
#include <cuda_runtime.h>
#include <cstdint>

#define MAX_CHILDS 65536
#define NUM_EDGES  1048576
#define HID        128
#define DIN        192
#define SPW        4          // segments per warp in edge_agg

// ---------------- device scratch (static, per rules; zero-initialized at load) ----------------
__device__ float   g_x[(size_t)MAX_CHILDS * HID];   // node features (32MB)
__device__ float   g_A[(size_t)MAX_CHILDS * HID];   // x @ W1 (src part)
__device__ float   g_B[(size_t)MAX_CHILDS * HID];   // x @ W2 (dst part)
__device__ int     g_cnt[MAX_CHILDS];               // zeroed by edge_agg iter2 after use
__device__ int     g_off[MAX_CHILDS];
__device__ int     g_cur[MAX_CHILDS];
__device__ int     g_bsum[256];
__device__ int     g_boff[256];
__device__ int     g_edst[NUM_EDGES + 8];           // dst per edge, CSR order (+pad for unclamped prefetch)
__device__ float4  g_eef[(size_t)(NUM_EDGES + 8) * 2]; // ef rows, CSR order (+pad)
__device__ unsigned g_max[3 * HID];                 // zeroed by final_kernel after use

typedef unsigned long long u64;

__device__ __forceinline__ u64 pack2(float lo, float hi) {
  u64 r; asm("mov.b64 %0, {%1, %2};" : "=l"(r) : "f"(lo), "f"(hi)); return r;
}
__device__ __forceinline__ void unpack2(u64 v, float& lo, float& hi) {
  asm("mov.b64 {%0, %1}, %2;" : "=f"(lo), "=f"(hi) : "l"(v));
}
__device__ __forceinline__ u64 fma2(u64 a, u64 b, u64 c) {
  u64 r; asm("fma.rn.f32x2 %0, %1, %2, %3;" : "=l"(r) : "l"(a), "l"(b), "l"(c)); return r;
}
__device__ __forceinline__ u64 add2(u64 a, u64 b) {
  u64 r; asm("add.rn.f32x2 %0, %1, %2;" : "=l"(r) : "l"(a), "l"(b)); return r;
}

// ---------------- CSR build ----------------
__global__ void hist_kernel(const int2* __restrict__ eidx) {
  int e = blockIdx.x * blockDim.x + threadIdx.x;
  if (e < NUM_EDGES) atomicAdd(&g_cnt[__ldcs(&eidx[e].x)], 1);
}

__global__ __launch_bounds__(256) void scan1_kernel() {
  __shared__ int sm[256];
  int t = threadIdx.x;
  sm[t] = g_cnt[blockIdx.x * 256 + t];
  __syncthreads();
#pragma unroll
  for (int d = 128; d > 0; d >>= 1) {
    if (t < d) sm[t] += sm[t + d];
    __syncthreads();
  }
  if (t == 0) g_bsum[blockIdx.x] = sm[0];
}

__global__ __launch_bounds__(256) void scan2_kernel() {
  __shared__ int sm[256];
  int t = threadIdx.x;
  sm[t] = g_bsum[t];
  __syncthreads();
#pragma unroll
  for (int d = 1; d < 256; d <<= 1) {
    int v = sm[t];
    int a = (t >= d) ? sm[t - d] : 0;
    __syncthreads();
    sm[t] = v + a;
    __syncthreads();
  }
  g_boff[t] = (t == 0) ? 0 : sm[t - 1];
}

__global__ __launch_bounds__(256) void scan3_kernel() {
  __shared__ int sm[256];
  int t = threadIdx.x;
  int i = blockIdx.x * 256 + t;
  int v = g_cnt[i];
  sm[t] = v;
  __syncthreads();
#pragma unroll
  for (int d = 1; d < 256; d <<= 1) {
    int x = sm[t];
    int a = (t >= d) ? sm[t - d] : 0;
    __syncthreads();
    sm[t] = x + a;
    __syncthreads();
  }
  int excl = sm[t] - v + g_boff[blockIdx.x];
  g_off[i] = excl;
  g_cur[i] = excl;
}

__global__ void scatter_kernel(const int2* __restrict__ eidx, const float* __restrict__ ef) {
  int e = blockIdx.x * blockDim.x + threadIdx.x;
  if (e < NUM_EDGES) {
    int2 p = __ldcs(&eidx[e]);
    const float4* s = (const float4*)(ef + (size_t)e * 8);
    float4 e0 = __ldcs(s);
    float4 e1 = __ldcs(s + 1);
    int pos = atomicAdd(&g_cur[p.x], 1);
    g_edst[pos] = p.y;
    __stcs(&g_eef[(size_t)pos * 2],     e0);
    __stcs(&g_eef[(size_t)pos * 2 + 1], e1);
  }
}

// ---------------- column max over g_x: float4, high MLP ----------------
__global__ __launch_bounds__(256) void colmax_kernel(int maxoff) {
  __shared__ __align__(16) float4 sm4[256];
  int tid = threadIdx.x;
  int cg = tid & 31;          // column group: cols cg*4..cg*4+3
  int rg = tid >> 5;          // row group 0..7
  int row0 = blockIdx.x * 256;
  float4 m = make_float4(0.f, 0.f, 0.f, 0.f);
#pragma unroll 8
  for (int i = 0; i < 32; i++) {
    int r = row0 + rg + i * 8;
    float4 v = __ldcs((const float4*)&g_x[(size_t)r * HID + cg * 4]);
    m.x = fmaxf(m.x, v.x); m.y = fmaxf(m.y, v.y);
    m.z = fmaxf(m.z, v.z); m.w = fmaxf(m.w, v.w);
  }
  sm4[tid] = m;
  __syncthreads();
  if (tid < 32) {
    float4 a = sm4[tid];
#pragma unroll
    for (int g = 1; g < 8; g++) {
      float4 b = sm4[tid + g * 32];
      a.x = fmaxf(a.x, b.x); a.y = fmaxf(a.y, b.y);
      a.z = fmaxf(a.z, b.z); a.w = fmaxf(a.w, b.w);
    }
    atomicMax(&g_max[maxoff + tid * 4],     __float_as_uint(a.x));
    atomicMax(&g_max[maxoff + tid * 4 + 1], __float_as_uint(a.y));
    atomicMax(&g_max[maxoff + tid * 4 + 2], __float_as_uint(a.z));
    atomicMax(&g_max[maxoff + tid * 4 + 3], __float_as_uint(a.w));
  }
}

// ---------------- child MLP: x = relu(cf @ Wc + b) * exists ----------------
// 128x128 tile, acc pairs along N, register-staged double-buffered smem.
__global__ __launch_bounds__(256) void child_gemm_kernel(
    const float* __restrict__ X, const float* __restrict__ W,
    const float* __restrict__ bias, const float* __restrict__ exists) {
  __shared__ __align__(16) float Xs[2][16][128];
  __shared__ __align__(16) float Ws[2][16][128];
  int tid = threadIdx.x;
  int tm = tid & 15, tn = tid >> 4;
  int m0 = tm * 8, n0 = tn * 8;
  int rowBase = blockIdx.x * 128;

  int xrowA = tid >> 2,          xkA = (tid & 3) << 2;
  int xrowB = (tid + 256) >> 2,  xkB = ((tid + 256) & 3) << 2;
  int wrA = tid >> 5,            wcA = (tid & 31) << 2;
  int wrB = wrA + 8;

  u64 acc[8][4];
#pragma unroll
  for (int m = 0; m < 8; m++)
#pragma unroll
    for (int np = 0; np < 4; np++) acc[m][np] = 0ull;

  float4 xa = *(const float4*)&X[(size_t)(rowBase + xrowA) * DIN + xkA];
  float4 xb = *(const float4*)&X[(size_t)(rowBase + xrowB) * DIN + xkB];
  float4 wa = *(const float4*)&W[(size_t)wrA * HID + wcA];
  float4 wb = *(const float4*)&W[(size_t)wrB * HID + wcA];
  Xs[0][xkA + 0][xrowA] = xa.x; Xs[0][xkA + 1][xrowA] = xa.y;
  Xs[0][xkA + 2][xrowA] = xa.z; Xs[0][xkA + 3][xrowA] = xa.w;
  Xs[0][xkB + 0][xrowB] = xb.x; Xs[0][xkB + 1][xrowB] = xb.y;
  Xs[0][xkB + 2][xrowB] = xb.z; Xs[0][xkB + 3][xrowB] = xb.w;
  *(float4*)&Ws[0][wrA][wcA] = wa;
  *(float4*)&Ws[0][wrB][wcA] = wb;
  __syncthreads();

#pragma unroll 1
  for (int c = 0; c < DIN / 16; c++) {
    int cur = c & 1, nxt = cur ^ 1;
    bool more = (c + 1) < DIN / 16;
    if (more) {
      int kt = (c + 1) * 16;
      xa = *(const float4*)&X[(size_t)(rowBase + xrowA) * DIN + kt + xkA];
      xb = *(const float4*)&X[(size_t)(rowBase + xrowB) * DIN + kt + xkB];
      wa = *(const float4*)&W[(size_t)(kt + wrA) * HID + wcA];
      wb = *(const float4*)&W[(size_t)(kt + wrB) * HID + wcA];
    }
#pragma unroll
    for (int k = 0; k < 16; k++) {
      float4 x0 = *(const float4*)&Xs[cur][k][m0];
      float4 x1 = *(const float4*)&Xs[cur][k][m0 + 4];
      u64 xp[8] = {pack2(x0.x, x0.x), pack2(x0.y, x0.y), pack2(x0.z, x0.z), pack2(x0.w, x0.w),
                   pack2(x1.x, x1.x), pack2(x1.y, x1.y), pack2(x1.z, x1.z), pack2(x1.w, x1.w)};
      ulonglong2 w0 = *(const ulonglong2*)&Ws[cur][k][n0];
      ulonglong2 w1 = *(const ulonglong2*)&Ws[cur][k][n0 + 4];
      u64 wp[4] = {w0.x, w0.y, w1.x, w1.y};
#pragma unroll
      for (int m = 0; m < 8; m++)
#pragma unroll
        for (int np = 0; np < 4; np++) acc[m][np] = fma2(xp[m], wp[np], acc[m][np]);
    }
    if (more) {
      Xs[nxt][xkA + 0][xrowA] = xa.x; Xs[nxt][xkA + 1][xrowA] = xa.y;
      Xs[nxt][xkA + 2][xrowA] = xa.z; Xs[nxt][xkA + 3][xrowA] = xa.w;
      Xs[nxt][xkB + 0][xrowB] = xb.x; Xs[nxt][xkB + 1][xrowB] = xb.y;
      Xs[nxt][xkB + 2][xrowB] = xb.z; Xs[nxt][xkB + 3][xrowB] = xb.w;
      *(float4*)&Ws[nxt][wrA][wcA] = wa;
      *(float4*)&Ws[nxt][wrB][wcA] = wb;
      __syncthreads();
    }
  }

  float4 b0 = *(const float4*)&bias[n0];
  float4 b1 = *(const float4*)&bias[n0 + 4];
  float bb[8] = {b0.x, b0.y, b0.z, b0.w, b1.x, b1.y, b1.z, b1.w};
#pragma unroll
  for (int m = 0; m < 8; m++) {
    int r = rowBase + m0 + m;
    float ex = exists[r];
    float o[8];
    unpack2(acc[m][0], o[0], o[1]); unpack2(acc[m][1], o[2], o[3]);
    unpack2(acc[m][2], o[4], o[5]); unpack2(acc[m][3], o[6], o[7]);
#pragma unroll
    for (int j = 0; j < 8; j++) o[j] = fmaxf(o[j] + bb[j], 0.f) * ex;
    *(float4*)&g_x[(size_t)r * HID + n0]     = make_float4(o[0], o[1], o[2], o[3]);
    *(float4*)&g_x[(size_t)r * HID + n0 + 4] = make_float4(o[4], o[5], o[6], o[7]);
  }
}

// ---------------- fused A/B GEMM, 128x64 N-split tiles: A = x@W1, B = x@W2 ----------------
// grid = (MAX_CHILDS/128)*2; even blocks do cols [0,64), odd blocks cols [64,128).
__global__ __launch_bounds__(256, 2) void gemm_ab_fused_kernel(
    const float* __restrict__ W1, const float* __restrict__ W2) {
  __shared__ __align__(16) float Xs[2][16][128];
  __shared__ __align__(16) float W1s[2][16][64];
  __shared__ __align__(16) float W2s[2][16][64];
  int tid = threadIdx.x;
  int rowBase = (blockIdx.x >> 1) * 128;
  int nBase = (blockIdx.x & 1) * 64;
  int tm = tid & 15, tn = tid >> 4;
  int m0 = tm * 8, n0 = tn * 4;

  int xrowA = tid >> 2,          xkA = (tid & 3) << 2;
  int xrowB = (tid + 256) >> 2,  xkB = ((tid + 256) & 3) << 2;
  int wr = tid >> 4,             wc = (tid & 15) << 2;

  u64 accA[8][2], accB[8][2];
#pragma unroll
  for (int m = 0; m < 8; m++) {
    accA[m][0] = 0ull; accA[m][1] = 0ull;
    accB[m][0] = 0ull; accB[m][1] = 0ull;
  }

  // preload chunk 0 into buffer 0
  float4 xa = *(const float4*)&g_x[(size_t)(rowBase + xrowA) * HID + xkA];
  float4 xb = *(const float4*)&g_x[(size_t)(rowBase + xrowB) * HID + xkB];
  float4 w1a = *(const float4*)&W1[(size_t)wr * HID + nBase + wc];
  float4 w2a = *(const float4*)&W2[(size_t)wr * HID + nBase + wc];
  Xs[0][xkA + 0][xrowA] = xa.x; Xs[0][xkA + 1][xrowA] = xa.y;
  Xs[0][xkA + 2][xrowA] = xa.z; Xs[0][xkA + 3][xrowA] = xa.w;
  Xs[0][xkB + 0][xrowB] = xb.x; Xs[0][xkB + 1][xrowB] = xb.y;
  Xs[0][xkB + 2][xrowB] = xb.z; Xs[0][xkB + 3][xrowB] = xb.w;
  *(float4*)&W1s[0][wr][wc] = w1a;
  *(float4*)&W2s[0][wr][wc] = w2a;
  __syncthreads();

#pragma unroll 1
  for (int c = 0; c < HID / 16; c++) {
    int cur = c & 1, nxt = cur ^ 1;
    bool more = (c + 1) < HID / 16;
    if (more) {
      int kt = (c + 1) * 16;
      xa  = *(const float4*)&g_x[(size_t)(rowBase + xrowA) * HID + kt + xkA];
      xb  = *(const float4*)&g_x[(size_t)(rowBase + xrowB) * HID + kt + xkB];
      w1a = *(const float4*)&W1[(size_t)(kt + wr) * HID + nBase + wc];
      w2a = *(const float4*)&W2[(size_t)(kt + wr) * HID + nBase + wc];
    }
#pragma unroll
    for (int k = 0; k < 16; k++) {
      float4 x0 = *(const float4*)&Xs[cur][k][m0];
      float4 x1 = *(const float4*)&Xs[cur][k][m0 + 4];
      u64 xp[8] = {pack2(x0.x, x0.x), pack2(x0.y, x0.y), pack2(x0.z, x0.z), pack2(x0.w, x0.w),
                   pack2(x1.x, x1.x), pack2(x1.y, x1.y), pack2(x1.z, x1.z), pack2(x1.w, x1.w)};
      ulonglong2 w1v = *(const ulonglong2*)&W1s[cur][k][n0];
      ulonglong2 w2v = *(const ulonglong2*)&W2s[cur][k][n0];
#pragma unroll
      for (int m = 0; m < 8; m++) {
        accA[m][0] = fma2(xp[m], w1v.x, accA[m][0]);
        accA[m][1] = fma2(xp[m], w1v.y, accA[m][1]);
        accB[m][0] = fma2(xp[m], w2v.x, accB[m][0]);
        accB[m][1] = fma2(xp[m], w2v.y, accB[m][1]);
      }
    }
    if (more) {
      Xs[nxt][xkA + 0][xrowA] = xa.x; Xs[nxt][xkA + 1][xrowA] = xa.y;
      Xs[nxt][xkA + 2][xrowA] = xa.z; Xs[nxt][xkA + 3][xrowA] = xa.w;
      Xs[nxt][xkB + 0][xrowB] = xb.x; Xs[nxt][xkB + 1][xrowB] = xb.y;
      Xs[nxt][xkB + 2][xrowB] = xb.z; Xs[nxt][xkB + 3][xrowB] = xb.w;
      *(float4*)&W1s[nxt][wr][wc] = w1a;
      *(float4*)&W2s[nxt][wr][wc] = w2a;
      __syncthreads();
    }
  }

#pragma unroll
  for (int m = 0; m < 8; m++) {
    int r = rowBase + m0 + m;
    float oa0, oa1, oa2, oa3, ob0, ob1, ob2, ob3;
    unpack2(accA[m][0], oa0, oa1); unpack2(accA[m][1], oa2, oa3);
    unpack2(accB[m][0], ob0, ob1); unpack2(accB[m][1], ob2, ob3);
    *(float4*)&g_A[(size_t)r * HID + nBase + n0] = make_float4(oa0, oa1, oa2, oa3);
    *(float4*)&g_B[(size_t)r * HID + nBase + n0] = make_float4(ob0, ob1, ob2, ob3);
  }
}

// ---------------- edge aggregation: 2-edge pipeline, SPW segments per warp ----------------
__global__ __launch_bounds__(256, 2) void edge_agg_kernel(
    const float* __restrict__ W3, const float* __restrict__ bias, int resetCnt) {
  int tid = threadIdx.x;
  int lane = tid & 31;
  int gw = (blockIdx.x * blockDim.x + tid) >> 5;
  int s0 = gw * SPW;
  int j0 = lane << 2;

  u64 w01[8], w23[8];
#pragma unroll
  for (int k = 0; k < 8; k++) {
    float4 w = *(const float4*)&W3[k * HID + j0];
    w01[k] = pack2(w.x, w.y);
    w23[k] = pack2(w.z, w.w);
  }
  float4 bbv = *(const float4*)&bias[j0];
  u64 b01 = pack2(bbv.x, bbv.y), b23 = pack2(bbv.z, bbv.w);

  // snapshot lens/begs FIRST, then (optionally) reset g_cnt for the next run
  int lens[SPW], begs[SPW];
#pragma unroll
  for (int q = 0; q < SPW; q++) { begs[q] = g_off[s0 + q]; lens[q] = g_cnt[s0 + q]; }
  if (resetCnt && lane < SPW) g_cnt[s0 + lane] = 0;

  for (int q = 0; q < SPW; q++) {
    int s = s0 + q;
    int beg = begs[q];
    int len = lens[q];
    float4 a = __ldcs((const float4*)&g_A[(size_t)s * HID + j0]);
    u64 ab01 = add2(pack2(a.x, a.y), b01);
    u64 ab23 = add2(pack2(a.z, a.w), b23);
    float4 acc1 = make_float4(0.f, 0.f, 0.f, 0.f);
    float4 acc2 = make_float4(0.f, 0.f, 0.f, 0.f);

    int dA  = __ldcs(&g_edst[beg]);
    int dB  = __ldcs(&g_edst[beg + 1]);
    int dA2 = __ldcs(&g_edst[beg + 2]);
    int dB2 = __ldcs(&g_edst[beg + 3]);
    ulonglong2 bvA = __ldg((const ulonglong2*)&g_B[(size_t)dA * HID + j0]);
    ulonglong2 bvB = __ldg((const ulonglong2*)&g_B[(size_t)dB * HID + j0]);
    float4 eA0 = __ldcs(&g_eef[(size_t)beg * 2]),       eA1 = __ldcs(&g_eef[(size_t)beg * 2 + 1]);
    float4 eB0 = __ldcs(&g_eef[(size_t)(beg + 1) * 2]), eB1 = __ldcs(&g_eef[(size_t)(beg + 1) * 2 + 1]);

    for (int t = 0; t < len; t += 2) {
      ulonglong2 bvA2 = __ldg((const ulonglong2*)&g_B[(size_t)dA2 * HID + j0]);
      ulonglong2 bvB2 = __ldg((const ulonglong2*)&g_B[(size_t)dB2 * HID + j0]);
      size_t pb = (size_t)(beg + t) * 2;
      float4 eA20 = __ldcs(&g_eef[pb + 4]), eA21 = __ldcs(&g_eef[pb + 5]);
      float4 eB20 = __ldcs(&g_eef[pb + 6]), eB21 = __ldcs(&g_eef[pb + 7]);
      int dA3 = __ldcs(&g_edst[beg + t + 4]);
      int dB3 = __ldcs(&g_edst[beg + t + 5]);

      u64 cA01 = ab01, cA23 = ab23, cB01 = ab01, cB23 = ab23;
      float evA[8] = {eA0.x, eA0.y, eA0.z, eA0.w, eA1.x, eA1.y, eA1.z, eA1.w};
      float evB[8] = {eB0.x, eB0.y, eB0.z, eB0.w, eB1.x, eB1.y, eB1.z, eB1.w};
#pragma unroll
      for (int k = 0; k < 8; k++) {
        u64 edA = pack2(evA[k], evA[k]);
        u64 edB = pack2(evB[k], evB[k]);
        cA01 = fma2(edA, w01[k], cA01);
        cB01 = fma2(edB, w01[k], cB01);
        cA23 = fma2(edA, w23[k], cA23);
        cB23 = fma2(edB, w23[k], cB23);
      }
      cA01 = add2(cA01, bvA.x); cA23 = add2(cA23, bvA.y);
      cB01 = add2(cB01, bvB.x); cB23 = add2(cB23, bvB.y);
      float a0, a1, a2, a3, q0, q1, q2, q3;
      unpack2(cA01, a0, a1); unpack2(cA23, a2, a3);
      unpack2(cB01, q0, q1); unpack2(cB23, q2, q3);
      acc1.x += fmaxf(a0, 0.f); acc1.y += fmaxf(a1, 0.f);
      acc1.z += fmaxf(a2, 0.f); acc1.w += fmaxf(a3, 0.f);
      if (t + 1 < len) {   // warp-uniform
        acc2.x += fmaxf(q0, 0.f); acc2.y += fmaxf(q1, 0.f);
        acc2.z += fmaxf(q2, 0.f); acc2.w += fmaxf(q3, 0.f);
      }

      bvA = bvA2; bvB = bvB2;
      eA0 = eA20; eA1 = eA21; eB0 = eB20; eB1 = eB21;
      dA2 = dA3; dB2 = dB3;
    }
    acc1.x += acc2.x; acc1.y += acc2.y; acc1.z += acc2.z; acc1.w += acc2.w;
    __stcs((float4*)&g_x[(size_t)s * HID + j0], acc1);
  }
}

// ---------------- final: out = relu(concat(maxes) @ Wp + bp); resets g_max ----------------
__global__ void final_kernel(const float* __restrict__ Wp, const float* __restrict__ bp,
                             float* __restrict__ out) {
  __shared__ float pf[384];
  int t = threadIdx.x;
  for (int k = t; k < 384; k += 128) pf[k] = __uint_as_float(g_max[k]);
  __syncthreads();
  for (int k = t; k < 384; k += 128) g_max[k] = 0u;   // state reset
  float acc = bp[t];
#pragma unroll 8
  for (int k = 0; k < 384; k++) acc = fmaf(pf[k], Wp[(size_t)k * HID + t], acc);
  out[t] = fmaxf(acc, 0.f);
}

// ---------------- launch ----------------
extern "C" void kernel_launch(void* const* d_in, const int* in_sizes, int n_in,
                              void* d_out, int out_size) {
  const float* child_feats  = (const float*)d_in[0];  // [65536,192]
  const float* child_exists = (const float*)d_in[1];  // [65536]
  const float* ef           = (const float*)d_in[2];  // [1M,8]
  const int2*  eidx         = (const int2*)d_in[3];   // [1M,2]
  const float* Wc           = (const float*)d_in[4];  // [192,128]
  const float* bc           = (const float*)d_in[5];  // [128]
  const float* We           = (const float*)d_in[6];  // [2,264,128]
  const float* be           = (const float*)d_in[7];  // [2,128]
  const float* Wp           = (const float*)d_in[8];  // [384,128]
  const float* bp           = (const float*)d_in[9];  // [128]
  float* out = (float*)d_out;

  const float* We0 = We;
  const float* We1 = We + (size_t)264 * HID;

  hist_kernel<<<NUM_EDGES / 256, 256>>>(eidx);                              // 1
  child_gemm_kernel<<<MAX_CHILDS / 128, 256>>>(child_feats, Wc, bc, child_exists); // 2
  colmax_kernel<<<MAX_CHILDS / 256, 256>>>(0);                              // 3
  gemm_ab_fused_kernel<<<(MAX_CHILDS / 128) * 2, 256>>>(We0, We0 + 128 * HID); // 4 (profiled)
  scan1_kernel<<<256, 256>>>();                                             // 5
  scan2_kernel<<<1, 256>>>();                                               // 6
  scan3_kernel<<<256, 256>>>();                                             // 7
  scatter_kernel<<<NUM_EDGES / 256, 256>>>(eidx, ef);                       // 8
  edge_agg_kernel<<<MAX_CHILDS / SPW / 8, 256>>>(We0 + 256 * HID, be, 0);   // 9
  colmax_kernel<<<MAX_CHILDS / 256, 256>>>(HID);                            // 10
  gemm_ab_fused_kernel<<<(MAX_CHILDS / 128) * 2, 256>>>(We1, We1 + 128 * HID); // 11
  edge_agg_kernel<<<MAX_CHILDS / SPW / 8, 256>>>(We1 + 256 * HID, be + HID, 1); // 12
  colmax_kernel<<<MAX_CHILDS / 256, 256>>>(2 * HID);                        // 13
  final_kernel<<<1, 128>>>(Wp, bp, out);                                    // 14
}

// round 15
// speedup vs baseline: 1.4115x; 1.4115x over previous
#include <cuda_runtime.h>
#include <cstdint>

#define MAX_CHILDS 65536
#define NUM_EDGES  1048576
#define HID        128
#define DIN        192
#define SPW        4          // segments per warp in edge_agg

// ---------------- device scratch (static, per rules; zero-initialized at load) ----------------
__device__ float   g_x[(size_t)MAX_CHILDS * HID];   // node features (32MB)
__device__ float   g_A[(size_t)MAX_CHILDS * HID];   // x @ W1 (src part)
__device__ float   g_B[(size_t)MAX_CHILDS * HID];   // x @ W2 (dst part)
__device__ int     g_cnt[MAX_CHILDS];               // zeroed by edge_agg iter2 after use
__device__ int     g_off[MAX_CHILDS];
__device__ int     g_cur[MAX_CHILDS];
__device__ int     g_bsum[256];
__device__ int     g_boff[256];
__device__ int     g_edst[NUM_EDGES + 8];           // dst BYTE offset per edge, CSR order (+pad)
__device__ float4  g_eef[(size_t)(NUM_EDGES + 8) * 2]; // ef rows, CSR order (+pad)
__device__ unsigned g_max[3 * HID];                 // zeroed by final_kernel after use

typedef unsigned long long u64;

__device__ __forceinline__ u64 pack2(float lo, float hi) {
  u64 r; asm("mov.b64 %0, {%1, %2};" : "=l"(r) : "f"(lo), "f"(hi)); return r;
}
__device__ __forceinline__ void unpack2(u64 v, float& lo, float& hi) {
  asm("mov.b64 {%0, %1}, %2;" : "=f"(lo), "=f"(hi) : "l"(v));
}
__device__ __forceinline__ u64 fma2(u64 a, u64 b, u64 c) {
  u64 r; asm("fma.rn.f32x2 %0, %1, %2, %3;" : "=l"(r) : "l"(a), "l"(b), "l"(c)); return r;
}
__device__ __forceinline__ u64 add2(u64 a, u64 b) {
  u64 r; asm("add.rn.f32x2 %0, %1, %2;" : "=l"(r) : "l"(a), "l"(b)); return r;
}

// ---------------- CSR build ----------------
__global__ void hist_kernel(const int2* __restrict__ eidx) {
  int e = blockIdx.x * blockDim.x + threadIdx.x;
  if (e < NUM_EDGES) atomicAdd(&g_cnt[__ldcs(&eidx[e].x)], 1);
}

__global__ __launch_bounds__(256) void scan1_kernel() {
  __shared__ int sm[256];
  int t = threadIdx.x;
  sm[t] = g_cnt[blockIdx.x * 256 + t];
  __syncthreads();
#pragma unroll
  for (int d = 128; d > 0; d >>= 1) {
    if (t < d) sm[t] += sm[t + d];
    __syncthreads();
  }
  if (t == 0) g_bsum[blockIdx.x] = sm[0];
}

__global__ __launch_bounds__(256) void scan2_kernel() {
  __shared__ int sm[256];
  int t = threadIdx.x;
  sm[t] = g_bsum[t];
  __syncthreads();
#pragma unroll
  for (int d = 1; d < 256; d <<= 1) {
    int v = sm[t];
    int a = (t >= d) ? sm[t - d] : 0;
    __syncthreads();
    sm[t] = v + a;
    __syncthreads();
  }
  g_boff[t] = (t == 0) ? 0 : sm[t - 1];
}

__global__ __launch_bounds__(256) void scan3_kernel() {
  __shared__ int sm[256];
  int t = threadIdx.x;
  int i = blockIdx.x * 256 + t;
  int v = g_cnt[i];
  sm[t] = v;
  __syncthreads();
#pragma unroll
  for (int d = 1; d < 256; d <<= 1) {
    int x = sm[t];
    int a = (t >= d) ? sm[t - d] : 0;
    __syncthreads();
    sm[t] = x + a;
    __syncthreads();
  }
  int excl = sm[t] - v + g_boff[blockIdx.x];
  g_off[i] = excl;
  g_cur[i] = excl;
}

__global__ void scatter_kernel(const int2* __restrict__ eidx, const float* __restrict__ ef) {
  int e = blockIdx.x * blockDim.x + threadIdx.x;
  if (e < NUM_EDGES) {
    int2 p = __ldcs(&eidx[e]);
    const float4* s = (const float4*)(ef + (size_t)e * 8);
    float4 e0 = __ldcs(s);
    float4 e1 = __ldcs(s + 1);
    int pos = atomicAdd(&g_cur[p.x], 1);
    g_edst[pos] = p.y * (HID * 4);          // BYTE offset into g_B
    __stcs(&g_eef[(size_t)pos * 2],     e0);
    __stcs(&g_eef[(size_t)pos * 2 + 1], e1);
  }
}

// ---------------- column max over g_x (R12-validated version) ----------------
__global__ __launch_bounds__(256) void colmax_kernel(int maxoff) {
  __shared__ float sm[256];
  int tid = threadIdx.x;
  int col = tid & 127;
  int half = tid >> 7;
  int row0 = blockIdx.x * 256;
  float m = 0.f;
#pragma unroll 4
  for (int r = row0 + half; r < row0 + 256; r += 2)
    m = fmaxf(m, __ldcs(&g_x[(size_t)r * HID + col]));
  sm[tid] = m;
  __syncthreads();
  if (tid < 128) {
    m = fmaxf(sm[tid], sm[tid + 128]);
    atomicMax(&g_max[maxoff + col], __float_as_uint(m));
  }
}

// ---------------- child MLP: x = relu(cf @ Wc + b) * exists ----------------
// 128x128 tile, acc pairs along N, register-staged double-buffered smem.
__global__ __launch_bounds__(256) void child_gemm_kernel(
    const float* __restrict__ X, const float* __restrict__ W,
    const float* __restrict__ bias, const float* __restrict__ exists) {
  __shared__ __align__(16) float Xs[2][16][128];
  __shared__ __align__(16) float Ws[2][16][128];
  int tid = threadIdx.x;
  int tm = tid & 15, tn = tid >> 4;
  int m0 = tm * 8, n0 = tn * 8;
  int rowBase = blockIdx.x * 128;

  int xrowA = tid >> 2,          xkA = (tid & 3) << 2;
  int xrowB = (tid + 256) >> 2,  xkB = ((tid + 256) & 3) << 2;
  int wrA = tid >> 5,            wcA = (tid & 31) << 2;
  int wrB = wrA + 8;

  u64 acc[8][4];
#pragma unroll
  for (int m = 0; m < 8; m++)
#pragma unroll
    for (int np = 0; np < 4; np++) acc[m][np] = 0ull;

  float4 xa = *(const float4*)&X[(size_t)(rowBase + xrowA) * DIN + xkA];
  float4 xb = *(const float4*)&X[(size_t)(rowBase + xrowB) * DIN + xkB];
  float4 wa = *(const float4*)&W[(size_t)wrA * HID + wcA];
  float4 wb = *(const float4*)&W[(size_t)wrB * HID + wcA];
  Xs[0][xkA + 0][xrowA] = xa.x; Xs[0][xkA + 1][xrowA] = xa.y;
  Xs[0][xkA + 2][xrowA] = xa.z; Xs[0][xkA + 3][xrowA] = xa.w;
  Xs[0][xkB + 0][xrowB] = xb.x; Xs[0][xkB + 1][xrowB] = xb.y;
  Xs[0][xkB + 2][xrowB] = xb.z; Xs[0][xkB + 3][xrowB] = xb.w;
  *(float4*)&Ws[0][wrA][wcA] = wa;
  *(float4*)&Ws[0][wrB][wcA] = wb;
  __syncthreads();

#pragma unroll 1
  for (int c = 0; c < DIN / 16; c++) {
    int cur = c & 1, nxt = cur ^ 1;
    bool more = (c + 1) < DIN / 16;
    if (more) {
      int kt = (c + 1) * 16;
      xa = *(const float4*)&X[(size_t)(rowBase + xrowA) * DIN + kt + xkA];
      xb = *(const float4*)&X[(size_t)(rowBase + xrowB) * DIN + kt + xkB];
      wa = *(const float4*)&W[(size_t)(kt + wrA) * HID + wcA];
      wb = *(const float4*)&W[(size_t)(kt + wrB) * HID + wcA];
    }
#pragma unroll
    for (int k = 0; k < 16; k++) {
      float4 x0 = *(const float4*)&Xs[cur][k][m0];
      float4 x1 = *(const float4*)&Xs[cur][k][m0 + 4];
      u64 xp[8] = {pack2(x0.x, x0.x), pack2(x0.y, x0.y), pack2(x0.z, x0.z), pack2(x0.w, x0.w),
                   pack2(x1.x, x1.x), pack2(x1.y, x1.y), pack2(x1.z, x1.z), pack2(x1.w, x1.w)};
      ulonglong2 w0 = *(const ulonglong2*)&Ws[cur][k][n0];
      ulonglong2 w1 = *(const ulonglong2*)&Ws[cur][k][n0 + 4];
      u64 wp[4] = {w0.x, w0.y, w1.x, w1.y};
#pragma unroll
      for (int m = 0; m < 8; m++)
#pragma unroll
        for (int np = 0; np < 4; np++) acc[m][np] = fma2(xp[m], wp[np], acc[m][np]);
    }
    if (more) {
      Xs[nxt][xkA + 0][xrowA] = xa.x; Xs[nxt][xkA + 1][xrowA] = xa.y;
      Xs[nxt][xkA + 2][xrowA] = xa.z; Xs[nxt][xkA + 3][xrowA] = xa.w;
      Xs[nxt][xkB + 0][xrowB] = xb.x; Xs[nxt][xkB + 1][xrowB] = xb.y;
      Xs[nxt][xkB + 2][xrowB] = xb.z; Xs[nxt][xkB + 3][xrowB] = xb.w;
      *(float4*)&Ws[nxt][wrA][wcA] = wa;
      *(float4*)&Ws[nxt][wrB][wcA] = wb;
      __syncthreads();
    }
  }

  float4 b0 = *(const float4*)&bias[n0];
  float4 b1 = *(const float4*)&bias[n0 + 4];
  float bb[8] = {b0.x, b0.y, b0.z, b0.w, b1.x, b1.y, b1.z, b1.w};
#pragma unroll
  for (int m = 0; m < 8; m++) {
    int r = rowBase + m0 + m;
    float ex = exists[r];
    float o[8];
    unpack2(acc[m][0], o[0], o[1]); unpack2(acc[m][1], o[2], o[3]);
    unpack2(acc[m][2], o[4], o[5]); unpack2(acc[m][3], o[6], o[7]);
#pragma unroll
    for (int j = 0; j < 8; j++) o[j] = fmaxf(o[j] + bb[j], 0.f) * ex;
    *(float4*)&g_x[(size_t)r * HID + n0]     = make_float4(o[0], o[1], o[2], o[3]);
    *(float4*)&g_x[(size_t)r * HID + n0 + 4] = make_float4(o[4], o[5], o[6], o[7]);
  }
}

// ---------------- fused A/B GEMM (R12-validated): A = x@W1, B = x@W2 ----------------
__global__ __launch_bounds__(256) void gemm_ab_fused_kernel(
    const float* __restrict__ W1, const float* __restrict__ W2) {
  __shared__ __align__(16) float Xs[2][16][128];
  __shared__ __align__(16) float W1s[2][16][128];
  __shared__ __align__(16) float W2s[2][16][128];
  int tid = threadIdx.x;
  int tm = tid & 15, tn = tid >> 4;
  int m0 = tm * 8, n0 = tn * 8;
  int rowBase = blockIdx.x * 128;

  int xrowA = tid >> 2,          xkA = (tid & 3) << 2;
  int xrowB = (tid + 256) >> 2,  xkB = ((tid + 256) & 3) << 2;
  int wrA = tid >> 5,            wcA = (tid & 31) << 2;
  int wrB = wrA + 8;

  u64 accA[8][4], accB[8][4];
#pragma unroll
  for (int m = 0; m < 8; m++)
#pragma unroll
    for (int np = 0; np < 4; np++) { accA[m][np] = 0ull; accB[m][np] = 0ull; }

  float4 xa = *(const float4*)&g_x[(size_t)(rowBase + xrowA) * HID + xkA];
  float4 xb = *(const float4*)&g_x[(size_t)(rowBase + xrowB) * HID + xkB];
  float4 w1a = *(const float4*)&W1[(size_t)wrA * HID + wcA];
  float4 w1b = *(const float4*)&W1[(size_t)wrB * HID + wcA];
  float4 w2a = *(const float4*)&W2[(size_t)wrA * HID + wcA];
  float4 w2b = *(const float4*)&W2[(size_t)wrB * HID + wcA];
  Xs[0][xkA + 0][xrowA] = xa.x; Xs[0][xkA + 1][xrowA] = xa.y;
  Xs[0][xkA + 2][xrowA] = xa.z; Xs[0][xkA + 3][xrowA] = xa.w;
  Xs[0][xkB + 0][xrowB] = xb.x; Xs[0][xkB + 1][xrowB] = xb.y;
  Xs[0][xkB + 2][xrowB] = xb.z; Xs[0][xkB + 3][xrowB] = xb.w;
  *(float4*)&W1s[0][wrA][wcA] = w1a;
  *(float4*)&W1s[0][wrB][wcA] = w1b;
  *(float4*)&W2s[0][wrA][wcA] = w2a;
  *(float4*)&W2s[0][wrB][wcA] = w2b;
  __syncthreads();

#pragma unroll 1
  for (int c = 0; c < HID / 16; c++) {
    int cur = c & 1, nxt = cur ^ 1;
    bool more = (c + 1) < HID / 16;
    if (more) {
      int kt = (c + 1) * 16;
      xa  = *(const float4*)&g_x[(size_t)(rowBase + xrowA) * HID + kt + xkA];
      xb  = *(const float4*)&g_x[(size_t)(rowBase + xrowB) * HID + kt + xkB];
      w1a = *(const float4*)&W1[(size_t)(kt + wrA) * HID + wcA];
      w1b = *(const float4*)&W1[(size_t)(kt + wrB) * HID + wcA];
      w2a = *(const float4*)&W2[(size_t)(kt + wrA) * HID + wcA];
      w2b = *(const float4*)&W2[(size_t)(kt + wrB) * HID + wcA];
    }
#pragma unroll
    for (int k = 0; k < 16; k++) {
      float4 x0 = *(const float4*)&Xs[cur][k][m0];
      float4 x1 = *(const float4*)&Xs[cur][k][m0 + 4];
      u64 xp[8] = {pack2(x0.x, x0.x), pack2(x0.y, x0.y), pack2(x0.z, x0.z), pack2(x0.w, x0.w),
                   pack2(x1.x, x1.x), pack2(x1.y, x1.y), pack2(x1.z, x1.z), pack2(x1.w, x1.w)};
      ulonglong2 wA0 = *(const ulonglong2*)&W1s[cur][k][n0];
      ulonglong2 wA1 = *(const ulonglong2*)&W1s[cur][k][n0 + 4];
      ulonglong2 wB0 = *(const ulonglong2*)&W2s[cur][k][n0];
      ulonglong2 wB1 = *(const ulonglong2*)&W2s[cur][k][n0 + 4];
      u64 w1p[4] = {wA0.x, wA0.y, wA1.x, wA1.y};
      u64 w2p[4] = {wB0.x, wB0.y, wB1.x, wB1.y};
#pragma unroll
      for (int m = 0; m < 8; m++) {
#pragma unroll
        for (int np = 0; np < 4; np++) {
          accA[m][np] = fma2(xp[m], w1p[np], accA[m][np]);
          accB[m][np] = fma2(xp[m], w2p[np], accB[m][np]);
        }
      }
    }
    if (more) {
      Xs[nxt][xkA + 0][xrowA] = xa.x; Xs[nxt][xkA + 1][xrowA] = xa.y;
      Xs[nxt][xkA + 2][xrowA] = xa.z; Xs[nxt][xkA + 3][xrowA] = xa.w;
      Xs[nxt][xkB + 0][xrowB] = xb.x; Xs[nxt][xkB + 1][xrowB] = xb.y;
      Xs[nxt][xkB + 2][xrowB] = xb.z; Xs[nxt][xkB + 3][xrowB] = xb.w;
      *(float4*)&W1s[nxt][wrA][wcA] = w1a;
      *(float4*)&W1s[nxt][wrB][wcA] = w1b;
      *(float4*)&W2s[nxt][wrA][wcA] = w2a;
      *(float4*)&W2s[nxt][wrB][wcA] = w2b;
      __syncthreads();
    }
  }

#pragma unroll
  for (int m = 0; m < 8; m++) {
    int r = rowBase + m0 + m;
    float oa[8], ob[8];
    unpack2(accA[m][0], oa[0], oa[1]); unpack2(accA[m][1], oa[2], oa[3]);
    unpack2(accA[m][2], oa[4], oa[5]); unpack2(accA[m][3], oa[6], oa[7]);
    unpack2(accB[m][0], ob[0], ob[1]); unpack2(accB[m][1], ob[2], ob[3]);
    unpack2(accB[m][2], ob[4], ob[5]); unpack2(accB[m][3], ob[6], ob[7]);
    *(float4*)&g_A[(size_t)r * HID + n0]     = make_float4(oa[0], oa[1], oa[2], oa[3]);
    *(float4*)&g_A[(size_t)r * HID + n0 + 4] = make_float4(oa[4], oa[5], oa[6], oa[7]);
    *(float4*)&g_B[(size_t)r * HID + n0]     = make_float4(ob[0], ob[1], ob[2], ob[3]);
    *(float4*)&g_B[(size_t)r * HID + n0 + 4] = make_float4(ob[4], ob[5], ob[6], ob[7]);
  }
}

// ---------------- edge aggregation: 2-edge pipeline, byte-offset dsts, ptr arith ----------------
__global__ __launch_bounds__(256, 2) void edge_agg_kernel(
    const float* __restrict__ W3, const float* __restrict__ bias, int resetCnt) {
  int tid = threadIdx.x;
  int lane = tid & 31;
  int gw = (blockIdx.x * blockDim.x + tid) >> 5;
  int s0 = gw * SPW;
  int j0 = lane << 2;
  const char* Bbase = (const char*)g_B + ((size_t)j0 << 2);   // + j0*4 bytes

  u64 w01[8], w23[8];
#pragma unroll
  for (int k = 0; k < 8; k++) {
    float4 w = *(const float4*)&W3[k * HID + j0];
    w01[k] = pack2(w.x, w.y);
    w23[k] = pack2(w.z, w.w);
  }
  float4 bbv = *(const float4*)&bias[j0];
  u64 b01 = pack2(bbv.x, bbv.y), b23 = pack2(bbv.z, bbv.w);

  // snapshot lens/begs FIRST, then (optionally) reset g_cnt for the next run
  int lens[SPW], begs[SPW];
#pragma unroll
  for (int q = 0; q < SPW; q++) { begs[q] = g_off[s0 + q]; lens[q] = g_cnt[s0 + q]; }
  if (resetCnt && lane < SPW) g_cnt[s0 + lane] = 0;

  for (int q = 0; q < SPW; q++) {
    int s = s0 + q;
    int beg = begs[q];
    int len = lens[q];
    float4 a = __ldcs((const float4*)&g_A[(size_t)s * HID + j0]);
    u64 ab01 = add2(pack2(a.x, a.y), b01);
    u64 ab23 = add2(pack2(a.z, a.w), b23);
    float4 acc1 = make_float4(0.f, 0.f, 0.f, 0.f);
    float4 acc2 = make_float4(0.f, 0.f, 0.f, 0.f);

    const int* dp = &g_edst[beg];
    const float4* ep = &g_eef[(size_t)beg * 2];

    int dA  = __ldcs(dp);
    int dB  = __ldcs(dp + 1);
    int dA2 = __ldcs(dp + 2);
    int dB2 = __ldcs(dp + 3);
    ulonglong2 bvA = __ldg((const ulonglong2*)(Bbase + dA));
    ulonglong2 bvB = __ldg((const ulonglong2*)(Bbase + dB));
    float4 eA0 = __ldcs(ep),     eA1 = __ldcs(ep + 1);
    float4 eB0 = __ldcs(ep + 2), eB1 = __ldcs(ep + 3);
    dp += 4;

    for (int t = 0; t < len; t += 2) {
      ulonglong2 bvA2 = __ldg((const ulonglong2*)(Bbase + dA2));
      ulonglong2 bvB2 = __ldg((const ulonglong2*)(Bbase + dB2));
      float4 eA20 = __ldcs(ep + 4), eA21 = __ldcs(ep + 5);
      float4 eB20 = __ldcs(ep + 6), eB21 = __ldcs(ep + 7);
      int dA3 = __ldcs(dp);
      int dB3 = __ldcs(dp + 1);
      dp += 2; ep += 4;

      u64 cA01 = ab01, cA23 = ab23, cB01 = ab01, cB23 = ab23;
      float evA[8] = {eA0.x, eA0.y, eA0.z, eA0.w, eA1.x, eA1.y, eA1.z, eA1.w};
      float evB[8] = {eB0.x, eB0.y, eB0.z, eB0.w, eB1.x, eB1.y, eB1.z, eB1.w};
#pragma unroll
      for (int k = 0; k < 8; k++) {
        u64 edA = pack2(evA[k], evA[k]);
        u64 edB = pack2(evB[k], evB[k]);
        cA01 = fma2(edA, w01[k], cA01);
        cB01 = fma2(edB, w01[k], cB01);
        cA23 = fma2(edA, w23[k], cA23);
        cB23 = fma2(edB, w23[k], cB23);
      }
      cA01 = add2(cA01, bvA.x); cA23 = add2(cA23, bvA.y);
      cB01 = add2(cB01, bvB.x); cB23 = add2(cB23, bvB.y);
      float a0, a1, a2, a3, q0, q1, q2, q3;
      unpack2(cA01, a0, a1); unpack2(cA23, a2, a3);
      unpack2(cB01, q0, q1); unpack2(cB23, q2, q3);
      acc1.x += fmaxf(a0, 0.f); acc1.y += fmaxf(a1, 0.f);
      acc1.z += fmaxf(a2, 0.f); acc1.w += fmaxf(a3, 0.f);
      if (t + 1 < len) {   // warp-uniform
        acc2.x += fmaxf(q0, 0.f); acc2.y += fmaxf(q1, 0.f);
        acc2.z += fmaxf(q2, 0.f); acc2.w += fmaxf(q3, 0.f);
      }

      bvA = bvA2; bvB = bvB2;
      eA0 = eA20; eA1 = eA21; eB0 = eB20; eB1 = eB21;
      dA2 = dA3; dB2 = dB3;
    }
    acc1.x += acc2.x; acc1.y += acc2.y; acc1.z += acc2.z; acc1.w += acc2.w;
    __stcs((float4*)&g_x[(size_t)s * HID + j0], acc1);
  }
}

// ---------------- final: out = relu(concat(maxes) @ Wp + bp); resets g_max ----------------
__global__ void final_kernel(const float* __restrict__ Wp, const float* __restrict__ bp,
                             float* __restrict__ out) {
  __shared__ float pf[384];
  int t = threadIdx.x;
  for (int k = t; k < 384; k += 128) pf[k] = __uint_as_float(g_max[k]);
  __syncthreads();
  for (int k = t; k < 384; k += 128) g_max[k] = 0u;   // state reset
  float acc = bp[t];
#pragma unroll 8
  for (int k = 0; k < 384; k++) acc = fmaf(pf[k], Wp[(size_t)k * HID + t], acc);
  out[t] = fmaxf(acc, 0.f);
}

// ---------------- launch ----------------
extern "C" void kernel_launch(void* const* d_in, const int* in_sizes, int n_in,
                              void* d_out, int out_size) {
  const float* child_feats  = (const float*)d_in[0];  // [65536,192]
  const float* child_exists = (const float*)d_in[1];  // [65536]
  const float* ef           = (const float*)d_in[2];  // [1M,8]
  const int2*  eidx         = (const int2*)d_in[3];   // [1M,2]
  const float* Wc           = (const float*)d_in[4];  // [192,128]
  const float* bc           = (const float*)d_in[5];  // [128]
  const float* We           = (const float*)d_in[6];  // [2,264,128]
  const float* be           = (const float*)d_in[7];  // [2,128]
  const float* Wp           = (const float*)d_in[8];  // [384,128]
  const float* bp           = (const float*)d_in[9];  // [128]
  float* out = (float*)d_out;

  const float* We0 = We;
  const float* We1 = We + (size_t)264 * HID;

  hist_kernel<<<NUM_EDGES / 256, 256>>>(eidx);                              // 1
  child_gemm_kernel<<<MAX_CHILDS / 128, 256>>>(child_feats, Wc, bc, child_exists); // 2
  colmax_kernel<<<MAX_CHILDS / 256, 256>>>(0);                              // 3
  gemm_ab_fused_kernel<<<MAX_CHILDS / 128, 256>>>(We0, We0 + 128 * HID);    // 4 (profiled)
  scan1_kernel<<<256, 256>>>();                                             // 5
  scan2_kernel<<<1, 256>>>();                                               // 6
  scan3_kernel<<<256, 256>>>();                                             // 7
  scatter_kernel<<<NUM_EDGES / 256, 256>>>(eidx, ef);                       // 8
  edge_agg_kernel<<<MAX_CHILDS / SPW / 8, 256>>>(We0 + 256 * HID, be, 0);   // 9
  colmax_kernel<<<MAX_CHILDS / 256, 256>>>(HID);                            // 10
  gemm_ab_fused_kernel<<<MAX_CHILDS / 128, 256>>>(We1, We1 + 128 * HID);    // 11
  edge_agg_kernel<<<MAX_CHILDS / SPW / 8, 256>>>(We1 + 256 * HID, be + HID, 1); // 12
  colmax_kernel<<<MAX_CHILDS / 256, 256>>>(2 * HID);                        // 13
  final_kernel<<<1, 128>>>(Wp, bp, out);                                    // 14
}